// round 3
// baseline (speedup 1.0000x reference)
#include <cuda_runtime.h>
#include <math.h>

typedef unsigned long long ull;

// Problem constants
#define NB   2
#define TT   1024
#define DD   1024
#define HH   16
#define DHH  64
#define WW   64
#define WIN  129

// GEMM tiling
#define BM 128
#define BN 128
#define BK 16

// Scratch (device globals: allocation-free per harness rules)
__device__ float g_q[NB * TT * DD];
__device__ float g_k[NB * TT * DD];
__device__ float g_v[NB * TT * DD];
__device__ float g_attn[NB * TT * DD];

// ---------------- packed f32x2 helpers (Blackwell FFMA2) ----------------
__device__ __forceinline__ ull pack2(float x, float y) {
    ull r;
    asm("mov.b64 %0, {%1, %2};" : "=l"(r) : "f"(x), "f"(y));
    return r;
}
__device__ __forceinline__ void unpack2(ull v, float& x, float& y) {
    asm("mov.b64 {%0, %1}, %2;" : "=f"(x), "=f"(y) : "l"(v));
}
__device__ __forceinline__ void fma2(ull& d, ull a, ull b) {
    asm("fma.rn.f32x2 %0, %1, %2, %0;" : "+l"(d) : "l"(a), "l"(b));
}

// ---------------- tiled SGEMM: C[M,N] = A[M,K] * B[N,K]^T + bias ----------------
// 256 threads, 128x128 block tile, 8x8 per thread, f32x2-packed accumulation.
__device__ __forceinline__ void gemm_body(
    const float* __restrict__ A, const float* __restrict__ B,
    const float* __restrict__ bias, float* __restrict__ C,
    int M, int N, int K)
{
    __shared__ __align__(16) float As[BK][BM + 4];
    __shared__ __align__(16) float Bs[BK][BN + 4];

    const int tid = threadIdx.x;
    const int tx = tid & 15;
    const int ty = tid >> 4;
    const int row0 = blockIdx.y * BM;
    const int col0 = blockIdx.x * BN;

    ull acc[8][4];
#pragma unroll
    for (int i = 0; i < 8; ++i)
#pragma unroll
        for (int j = 0; j < 4; ++j) acc[i][j] = 0ull;

    for (int k0 = 0; k0 < K; k0 += BK) {
        // Load A & B tiles (K-major rows -> transposed into [BK][128] smem)
#pragma unroll
        for (int i = 0; i < 2; ++i) {
            int idx = tid + (i << 8);         // 0..511
            int r   = idx >> 2;               // 0..127
            int kc  = (idx & 3) << 2;         // 0,4,8,12
            float4 av = *(const float4*)(A + (size_t)(row0 + r) * K + k0 + kc);
            As[kc + 0][r] = av.x; As[kc + 1][r] = av.y;
            As[kc + 2][r] = av.z; As[kc + 3][r] = av.w;
            float4 bv = *(const float4*)(B + (size_t)(col0 + r) * K + k0 + kc);
            Bs[kc + 0][r] = bv.x; Bs[kc + 1][r] = bv.y;
            Bs[kc + 2][r] = bv.z; Bs[kc + 3][r] = bv.w;
        }
        __syncthreads();

#pragma unroll
        for (int kk = 0; kk < BK; ++kk) {
            float4 a0 = *(const float4*)&As[kk][ty * 8];
            float4 a1 = *(const float4*)&As[kk][ty * 8 + 4];
            ulonglong2 b01 = *(const ulonglong2*)&Bs[kk][tx * 8];
            ulonglong2 b23 = *(const ulonglong2*)&Bs[kk][tx * 8 + 4];
            ull b2[4] = { b01.x, b01.y, b23.x, b23.y };
            float a[8] = { a0.x, a0.y, a0.z, a0.w, a1.x, a1.y, a1.z, a1.w };
#pragma unroll
            for (int i = 0; i < 8; ++i) {
                ull a2 = pack2(a[i], a[i]);
#pragma unroll
                for (int j = 0; j < 4; ++j) fma2(acc[i][j], a2, b2[j]);
            }
        }
        __syncthreads();
    }

    // Epilogue: unpack, add bias, store
    float bs[8];
#pragma unroll
    for (int j = 0; j < 8; ++j) bs[j] = bias[col0 + tx * 8 + j];
#pragma unroll
    for (int i = 0; i < 8; ++i) {
        float r[8];
#pragma unroll
        for (int j = 0; j < 4; ++j) unpack2(acc[i][j], r[2 * j], r[2 * j + 1]);
        float* cp = C + (size_t)(row0 + ty * 8 + i) * N + col0 + tx * 8;
        *(float4*)cp       = make_float4(r[0] + bs[0], r[1] + bs[1], r[2] + bs[2], r[3] + bs[3]);
        *(float4*)(cp + 4) = make_float4(r[4] + bs[4], r[5] + bs[5], r[6] + bs[6], r[7] + bs[7]);
    }
}

// QKV fused: blockIdx.z selects which projection; writes device-global scratch.
__global__ __launch_bounds__(256, 2) void gemm_qkv_kernel(
    const float* __restrict__ x,
    const float* __restrict__ wq, const float* __restrict__ bq,
    const float* __restrict__ wk, const float* __restrict__ bk,
    const float* __restrict__ wv, const float* __restrict__ bv,
    int M, int N, int K)
{
    const float* B; const float* bias; float* C;
    if (blockIdx.z == 0)      { B = wq; bias = bq; C = g_q; }
    else if (blockIdx.z == 1) { B = wk; bias = bk; C = g_k; }
    else                      { B = wv; bias = bv; C = g_v; }
    gemm_body(x, B, bias, C, M, N, K);
}

__global__ __launch_bounds__(256, 2) void gemm_out_kernel(
    const float* __restrict__ wo, const float* __restrict__ bo,
    float* __restrict__ out, int M, int N, int K)
{
    gemm_body(g_attn, wo, bo, out, M, N, K);
}

// ---------------- windowed attention: one warp per (n, h, t) ----------------
// Lanes own the dh dimension (2 floats each) -> coalesced K/V loads.
// Scores via butterfly reduce; softmax over 129 window positions in smem.
__global__ __launch_bounds__(128) void attn_kernel()
{
    __shared__ float sbuf[4][WIN + 3];
    const float* __restrict__ q = g_q;
    const float* __restrict__ k = g_k;
    const float* __restrict__ v = g_v;
    float* __restrict__ o = g_attn;

    const int lane = threadIdx.x & 31;
    const int warp = threadIdx.x >> 5;
    int gw = blockIdx.x * 4 + warp;      // 0 .. N*H*T-1
    int t  = gw & (TT - 1);
    int nh = gw >> 10;                   // T = 1024
    int h  = nh & (HH - 1);
    int n  = nh >> 4;                    // H = 16

    const size_t head_off = (size_t)n * TT * DD + (size_t)h * DHH;
    const float2* k2 = (const float2*)(k + head_off);
    const float2* v2 = (const float2*)(v + head_off);
    const int ld2 = DD / 2;

    float2 qv = ((const float2*)(q + head_off + (size_t)t * DD))[lane];
    const float scale = 0.125f;          // 1/sqrt(64)
    qv.x *= scale; qv.y *= scale;

    // --- scores ---
#pragma unroll 4
    for (int w = 0; w < WIN; ++w) {
        int pos = t + w - WW;
        int cp  = min(max(pos, 0), TT - 1);
        float2 kk = k2[(size_t)cp * ld2 + lane];
        float s = qv.x * kk.x + qv.y * kk.y;
#pragma unroll
        for (int off = 16; off > 0; off >>= 1)
            s += __shfl_xor_sync(0xffffffffu, s, off);
        if (pos != cp) s = -INFINITY;    // out-of-range window position
        if (lane == 0) sbuf[warp][w] = s;
    }
    __syncwarp();

    // --- softmax over the 129 scores ---
    float sc[5];
#pragma unroll
    for (int c = 0; c < 5; ++c) {
        int w = c * 32 + lane;
        sc[c] = (w < WIN) ? sbuf[warp][w] : -INFINITY;
    }
    float m = sc[0];
#pragma unroll
    for (int c = 1; c < 5; ++c) m = fmaxf(m, sc[c]);
#pragma unroll
    for (int off = 16; off > 0; off >>= 1)
        m = fmaxf(m, __shfl_xor_sync(0xffffffffu, m, off));
    float sum = 0.f;
#pragma unroll
    for (int c = 0; c < 5; ++c) {
        int w = c * 32 + lane;
        float e = __expf(sc[c] - m);     // exp(-inf)=0 handles invalid/masked
        if (w < WIN) { sbuf[warp][w] = e; sum += e; }
    }
#pragma unroll
    for (int off = 16; off > 0; off >>= 1)
        sum += __shfl_xor_sync(0xffffffffu, sum, off);
    float inv = 1.0f / sum;
    __syncwarp();

    // --- P @ V ---
    float2 acc = make_float2(0.f, 0.f);
#pragma unroll 4
    for (int w = 0; w < WIN; ++w) {
        int pos = t + w - WW;
        int cp  = min(max(pos, 0), TT - 1);
        float p = sbuf[warp][w];         // 0 for invalid positions
        float2 vv = v2[(size_t)cp * ld2 + lane];
        acc.x += p * vv.x;
        acc.y += p * vv.y;
    }
    ((float2*)(o + head_off + (size_t)t * DD))[lane] =
        make_float2(acc.x * inv, acc.y * inv);
}

// ---------------- launch ----------------
extern "C" void kernel_launch(void* const* d_in, const int* in_sizes, int n_in,
                              void* d_out, int out_size)
{
    const float* x  = (const float*)d_in[0];
    const float* wq = (const float*)d_in[1];
    const float* bq = (const float*)d_in[2];
    const float* wk = (const float*)d_in[3];
    const float* bk = (const float*)d_in[4];
    const float* wv = (const float*)d_in[5];
    const float* bv = (const float*)d_in[6];
    const float* wo = (const float*)d_in[7];
    const float* bo = (const float*)d_in[8];

    const int M = NB * TT;   // 2048
    const int N = DD;        // 1024
    const int K = DD;        // 1024

    dim3 gq(N / BN, M / BM, 3);
    gemm_qkv_kernel<<<gq, 256>>>(x, wq, bq, wk, bk, wv, bv, M, N, K);

    attn_kernel<<<(NB * HH * TT) / 4, 128>>>();

    dim3 go(N / BN, M / BM);
    gemm_out_kernel<<<go, 256>>>(wo, bo, (float*)d_out, M, N, K);
}

// round 5
// speedup vs baseline: 1.9519x; 1.9519x over previous
#include <cuda_runtime.h>
#include <math.h>
#include <stdint.h>

// Problem constants
#define NB   2
#define TT   1024
#define DD   1024
#define HH   16
#define DHH  64
#define WW   64
#define WIN  129

// GEMM dims
#define GM 2048
#define GN 1024
#define GK 1024
// Tiling
#define BM 128
#define BN 128
#define BK 32
#define SROW 36                 // padded smem row stride (floats) -> conflict-free LDS
#define NITER (GK / BK)         // 32
#define SMEM_FLOATS (2 * 2 * BM * SROW)      // 2 buffers x (A+B) x 128 x 36
#define SMEM_BYTES  (SMEM_FLOATS * 4)        // 73728

// Scratch (device globals: allocation-free per harness rules)
__device__ float g_q[NB * TT * DD];
__device__ float g_k[NB * TT * DD];
__device__ float g_v[NB * TT * DD];
__device__ float g_attn[NB * TT * DD];

__device__ __forceinline__ float to_tf32(float x) {
    float r;
    asm("cvt.rna.tf32.f32 %0, %1;" : "=f"(r) : "f"(x));
    return r;
}

__device__ __forceinline__ void mma_16x8x8_tf32(float* d, const uint32_t* a,
                                                const uint32_t* b) {
    asm volatile(
        "mma.sync.aligned.m16n8k8.row.col.f32.tf32.tf32.f32 "
        "{%0,%1,%2,%3}, {%4,%5,%6,%7}, {%8,%9}, {%0,%1,%2,%3};"
        : "+f"(d[0]), "+f"(d[1]), "+f"(d[2]), "+f"(d[3])
        : "r"(a[0]), "r"(a[1]), "r"(a[2]), "r"(a[3]),
          "r"(b[0]), "r"(b[1]));
}

// ---------------------------------------------------------------------------
// tf32 mma.sync GEMM: C[M,N] = A[M,K] @ B[N,K]^T + bias
// 256 threads, 128x128 CTA tile, BK=32, warp grid 2(M) x 4(N), warp tile 64x32.
// ---------------------------------------------------------------------------
__device__ __forceinline__ void gemm_tc_body(
    const float* __restrict__ A, const float* __restrict__ B,
    const float* __restrict__ bias, float* __restrict__ C)
{
    extern __shared__ float smem[];
    float* Asm = smem;                       // [2][BM*SROW]
    float* Bsm = smem + 2 * BM * SROW;       // [2][BM*SROW]

    const int tid  = threadIdx.x;
    const int lane = tid & 31;
    const int wid  = tid >> 5;
    const int wm   = wid >> 2;               // 0..1  (M group of 64)
    const int wn   = wid & 3;                // 0..3  (N group of 32)
    const int row0 = blockIdx.y * BM;
    const int col0 = blockIdx.x * BN;

    const int lrow = tid >> 3;               // 0..31 (load row within group of 32)
    const int lq   = tid & 7;                // float4 index within a 32-float row

    float acc[4][4][4];
#pragma unroll
    for (int m = 0; m < 4; ++m)
#pragma unroll
        for (int n = 0; n < 4; ++n)
#pragma unroll
            for (int e = 0; e < 4; ++e) acc[m][n][e] = 0.f;

    float4 pa[4], pb[4];

    // prologue: load tile 0
#pragma unroll
    for (int p = 0; p < 4; ++p) {
        int r = p * 32 + lrow;
        pa[p] = *(const float4*)(A + (size_t)(row0 + r) * GK + lq * 4);
        pb[p] = *(const float4*)(B + (size_t)(col0 + r) * GK + lq * 4);
    }
#pragma unroll
    for (int p = 0; p < 4; ++p) {
        int r = p * 32 + lrow;
        float4 va = pa[p], vb = pb[p];
        va.x = to_tf32(va.x); va.y = to_tf32(va.y);
        va.z = to_tf32(va.z); va.w = to_tf32(va.w);
        vb.x = to_tf32(vb.x); vb.y = to_tf32(vb.y);
        vb.z = to_tf32(vb.z); vb.w = to_tf32(vb.w);
        *(float4*)(Asm + r * SROW + lq * 4) = va;
        *(float4*)(Bsm + r * SROW + lq * 4) = vb;
    }
    __syncthreads();

    const int c  = lane & 3;
    const int r4 = lane >> 2;

    for (int i = 0; i < NITER; ++i) {
        const int buf = i & 1;
        const float* Ab = Asm + buf * (BM * SROW);
        const float* Bb = Bsm + buf * (BM * SROW);

        if (i + 1 < NITER) {
            const int k0 = (i + 1) * BK;
#pragma unroll
            for (int p = 0; p < 4; ++p) {
                int r = p * 32 + lrow;
                pa[p] = *(const float4*)(A + (size_t)(row0 + r) * GK + k0 + lq * 4);
                pb[p] = *(const float4*)(B + (size_t)(col0 + r) * GK + k0 + lq * 4);
            }
        }

        const uint32_t* Au = (const uint32_t*)(Ab + (wm * 64 + r4) * SROW + c);
        const uint32_t* Bu = (const uint32_t*)(Bb + (wn * 32 + r4) * SROW + c);

#pragma unroll
        for (int kk = 0; kk < 4; ++kk) {
            uint32_t af[4][4], bf[4][2];
            const int ko = kk * 8;
#pragma unroll
            for (int m = 0; m < 4; ++m) {
                af[m][0] = Au[(m * 16 + 0) * SROW + ko + 0];
                af[m][1] = Au[(m * 16 + 8) * SROW + ko + 0];
                af[m][2] = Au[(m * 16 + 0) * SROW + ko + 4];
                af[m][3] = Au[(m * 16 + 8) * SROW + ko + 4];
            }
#pragma unroll
            for (int n = 0; n < 4; ++n) {
                bf[n][0] = Bu[n * 8 * SROW + ko + 0];
                bf[n][1] = Bu[n * 8 * SROW + ko + 4];
            }
#pragma unroll
            for (int m = 0; m < 4; ++m)
#pragma unroll
                for (int n = 0; n < 4; ++n)
                    mma_16x8x8_tf32(acc[m][n], af[m], bf[n]);
        }

        if (i + 1 < NITER) {
            float* Aw = Asm + (buf ^ 1) * (BM * SROW);
            float* Bw = Bsm + (buf ^ 1) * (BM * SROW);
#pragma unroll
            for (int p = 0; p < 4; ++p) {
                int r = p * 32 + lrow;
                float4 va = pa[p], vb = pb[p];
                va.x = to_tf32(va.x); va.y = to_tf32(va.y);
                va.z = to_tf32(va.z); va.w = to_tf32(va.w);
                vb.x = to_tf32(vb.x); vb.y = to_tf32(vb.y);
                vb.z = to_tf32(vb.z); vb.w = to_tf32(vb.w);
                *(float4*)(Aw + r * SROW + lq * 4) = va;
                *(float4*)(Bw + r * SROW + lq * 4) = vb;
            }
            __syncthreads();
        }
    }

    // epilogue: C[row][col] += bias; fragment c0,c1 at (r4, 2c), (r4, 2c+1); c2,c3 at r4+8
#pragma unroll
    for (int m = 0; m < 4; ++m) {
#pragma unroll
        for (int h = 0; h < 2; ++h) {
            const int grow = row0 + wm * 64 + m * 16 + r4 + 8 * h;
            float* crow = C + (size_t)grow * GN;
#pragma unroll
            for (int n = 0; n < 4; ++n) {
                const int gcol = col0 + wn * 32 + n * 8 + 2 * c;
                float2 o;
                o.x = acc[m][n][2 * h + 0] + __ldg(&bias[gcol + 0]);
                o.y = acc[m][n][2 * h + 1] + __ldg(&bias[gcol + 1]);
                *(float2*)(crow + gcol) = o;
            }
        }
    }
}

__global__ __launch_bounds__(256, 2) void gemm_qkv_tc(
    const float* __restrict__ x,
    const float* __restrict__ wq, const float* __restrict__ bq,
    const float* __restrict__ wk, const float* __restrict__ bk,
    const float* __restrict__ wv, const float* __restrict__ bv)
{
    const float* B; const float* bias; float* C;
    if (blockIdx.z == 0)      { B = wq; bias = bq; C = g_q; }
    else if (blockIdx.z == 1) { B = wk; bias = bk; C = g_k; }
    else                      { B = wv; bias = bv; C = g_v; }
    gemm_tc_body(x, B, bias, C);
}

__global__ __launch_bounds__(256, 2) void gemm_out_tc(
    const float* __restrict__ wo, const float* __restrict__ bo,
    float* __restrict__ out)
{
    gemm_tc_body(g_attn, wo, bo, out);
}

// ---------------- windowed attention: one warp per (n, h, t) ----------------
__global__ __launch_bounds__(128) void attn_kernel()
{
    __shared__ float sbuf[4][WIN + 3];
    const float* __restrict__ q = g_q;
    const float* __restrict__ k = g_k;
    const float* __restrict__ v = g_v;
    float* __restrict__ o = g_attn;

    const int lane = threadIdx.x & 31;
    const int warp = threadIdx.x >> 5;
    int gw = blockIdx.x * 4 + warp;      // 0 .. N*H*T-1
    int t  = gw & (TT - 1);
    int nh = gw >> 10;                   // T = 1024
    int h  = nh & (HH - 1);
    int n  = nh >> 4;                    // H = 16

    const size_t head_off = (size_t)n * TT * DD + (size_t)h * DHH;
    const float2* k2 = (const float2*)(k + head_off);
    const float2* v2 = (const float2*)(v + head_off);
    const int ld2 = DD / 2;

    float2 qv = ((const float2*)(q + head_off + (size_t)t * DD))[lane];
    const float scale = 0.125f;          // 1/sqrt(64)
    qv.x *= scale; qv.y *= scale;

    // --- scores ---
#pragma unroll 4
    for (int w = 0; w < WIN; ++w) {
        int pos = t + w - WW;
        int cp  = min(max(pos, 0), TT - 1);
        float2 kk = k2[(size_t)cp * ld2 + lane];
        float s = qv.x * kk.x + qv.y * kk.y;
#pragma unroll
        for (int off = 16; off > 0; off >>= 1)
            s += __shfl_xor_sync(0xffffffffu, s, off);
        if (pos != cp) s = -INFINITY;    // out-of-range window position
        if (lane == 0) sbuf[warp][w] = s;
    }
    __syncwarp();

    // --- softmax over the 129 scores ---
    float sc[5];
#pragma unroll
    for (int cI = 0; cI < 5; ++cI) {
        int w = cI * 32 + lane;
        sc[cI] = (w < WIN) ? sbuf[warp][w] : -INFINITY;
    }
    float m = sc[0];
#pragma unroll
    for (int cI = 1; cI < 5; ++cI) m = fmaxf(m, sc[cI]);
#pragma unroll
    for (int off = 16; off > 0; off >>= 1)
        m = fmaxf(m, __shfl_xor_sync(0xffffffffu, m, off));
    float sum = 0.f;
#pragma unroll
    for (int cI = 0; cI < 5; ++cI) {
        int w = cI * 32 + lane;
        float e = __expf(sc[cI] - m);    // exp(-inf)=0 handles invalid/masked
        if (w < WIN) { sbuf[warp][w] = e; sum += e; }
    }
#pragma unroll
    for (int off = 16; off > 0; off >>= 1)
        sum += __shfl_xor_sync(0xffffffffu, sum, off);
    float inv = 1.0f / sum;
    __syncwarp();

    // --- P @ V ---
    float2 acc = make_float2(0.f, 0.f);
#pragma unroll 4
    for (int w = 0; w < WIN; ++w) {
        int pos = t + w - WW;
        int cp  = min(max(pos, 0), TT - 1);
        float p = sbuf[warp][w];         // 0 for invalid positions
        float2 vv = v2[(size_t)cp * ld2 + lane];
        acc.x += p * vv.x;
        acc.y += p * vv.y;
    }
    ((float2*)(o + head_off + (size_t)t * DD))[lane] =
        make_float2(acc.x * inv, acc.y * inv);
}

// ---------------- launch ----------------
extern "C" void kernel_launch(void* const* d_in, const int* in_sizes, int n_in,
                              void* d_out, int out_size)
{
    const float* x  = (const float*)d_in[0];
    const float* wq = (const float*)d_in[1];
    const float* bq = (const float*)d_in[2];
    const float* wk = (const float*)d_in[3];
    const float* bk = (const float*)d_in[4];
    const float* wv = (const float*)d_in[5];
    const float* bv = (const float*)d_in[6];
    const float* wo = (const float*)d_in[7];
    const float* bo = (const float*)d_in[8];

    cudaFuncSetAttribute(gemm_qkv_tc,
                         cudaFuncAttributeMaxDynamicSharedMemorySize, SMEM_BYTES);
    cudaFuncSetAttribute(gemm_out_tc,
                         cudaFuncAttributeMaxDynamicSharedMemorySize, SMEM_BYTES);

    dim3 gq(GN / BN, GM / BM, 3);
    gemm_qkv_tc<<<gq, 256, SMEM_BYTES>>>(x, wq, bq, wk, bk, wv, bv);

    attn_kernel<<<(NB * HH * TT) / 4, 128>>>();

    dim3 go(GN / BN, GM / BM);
    gemm_out_tc<<<go, 256, SMEM_BYTES>>>(wo, bo, (float*)d_out);
}

// round 6
// speedup vs baseline: 2.7558x; 1.4118x over previous
#include <cuda_runtime.h>
#include <math.h>
#include <stdint.h>

// Problem constants
#define NB   2
#define TT   1024
#define DD   1024
#define HH   16
#define DHH  64
#define WW   64
#define WIN  129

// GEMM dims
#define GM 2048
#define GN 1024
#define GK 1024
// Tiling
#define BM 128
#define BN 128
#define BK 32
#define SROW 36
#define NITER (GK / BK)
#define SMEM_FLOATS (2 * 2 * BM * SROW)
#define SMEM_BYTES  (SMEM_FLOATS * 4)        // 73728

// Attention tiling: CTA = (n, h, 64-t block); window union = 192 positions
#define AQ_STRIDE 66
#define AK_STRIDE 66
#define AV_STRIDE 68
#define AP_STRIDE 196
#define SM_Q   0
#define SM_K   4224                      // 64*66
#define SM_V   16896                     // + 192*66
#define SM_RED 29952                     // + 192*68
#define SM_MAX 30976                     // + 64*16
#define SM_INV 31040
#define ATT_SMEM_BYTES (31104 * 4)       // 124416

// Scratch (device globals: allocation-free per harness rules)
__device__ float g_q[NB * TT * DD];
__device__ float g_k[NB * TT * DD];
__device__ float g_v[NB * TT * DD];
__device__ float g_attn[NB * TT * DD];

__device__ __forceinline__ float to_tf32(float x) {
    float r;
    asm("cvt.rna.tf32.f32 %0, %1;" : "=f"(r) : "f"(x));
    return r;
}

__device__ __forceinline__ void mma_16x8x8_tf32(float* d, const uint32_t* a,
                                                const uint32_t* b) {
    asm volatile(
        "mma.sync.aligned.m16n8k8.row.col.f32.tf32.tf32.f32 "
        "{%0,%1,%2,%3}, {%4,%5,%6,%7}, {%8,%9}, {%0,%1,%2,%3};"
        : "+f"(d[0]), "+f"(d[1]), "+f"(d[2]), "+f"(d[3])
        : "r"(a[0]), "r"(a[1]), "r"(a[2]), "r"(a[3]),
          "r"(b[0]), "r"(b[1]));
}

// ---------------------------------------------------------------------------
// tf32 mma.sync GEMM: C[M,N] = A[M,K] @ B[N,K]^T + bias   (unchanged from R5)
// ---------------------------------------------------------------------------
__device__ __forceinline__ void gemm_tc_body(
    const float* __restrict__ A, const float* __restrict__ B,
    const float* __restrict__ bias, float* __restrict__ C)
{
    extern __shared__ float smem[];
    float* Asm = smem;
    float* Bsm = smem + 2 * BM * SROW;

    const int tid  = threadIdx.x;
    const int lane = tid & 31;
    const int wid  = tid >> 5;
    const int wm   = wid >> 2;
    const int wn   = wid & 3;
    const int row0 = blockIdx.y * BM;
    const int col0 = blockIdx.x * BN;

    const int lrow = tid >> 3;
    const int lq   = tid & 7;

    float acc[4][4][4];
#pragma unroll
    for (int m = 0; m < 4; ++m)
#pragma unroll
        for (int n = 0; n < 4; ++n)
#pragma unroll
            for (int e = 0; e < 4; ++e) acc[m][n][e] = 0.f;

    float4 pa[4], pb[4];

#pragma unroll
    for (int p = 0; p < 4; ++p) {
        int r = p * 32 + lrow;
        pa[p] = *(const float4*)(A + (size_t)(row0 + r) * GK + lq * 4);
        pb[p] = *(const float4*)(B + (size_t)(col0 + r) * GK + lq * 4);
    }
#pragma unroll
    for (int p = 0; p < 4; ++p) {
        int r = p * 32 + lrow;
        float4 va = pa[p], vb = pb[p];
        va.x = to_tf32(va.x); va.y = to_tf32(va.y);
        va.z = to_tf32(va.z); va.w = to_tf32(va.w);
        vb.x = to_tf32(vb.x); vb.y = to_tf32(vb.y);
        vb.z = to_tf32(vb.z); vb.w = to_tf32(vb.w);
        *(float4*)(Asm + r * SROW + lq * 4) = va;
        *(float4*)(Bsm + r * SROW + lq * 4) = vb;
    }
    __syncthreads();

    const int c  = lane & 3;
    const int r4 = lane >> 2;

    for (int i = 0; i < NITER; ++i) {
        const int buf = i & 1;
        const float* Ab = Asm + buf * (BM * SROW);
        const float* Bb = Bsm + buf * (BM * SROW);

        if (i + 1 < NITER) {
            const int k0 = (i + 1) * BK;
#pragma unroll
            for (int p = 0; p < 4; ++p) {
                int r = p * 32 + lrow;
                pa[p] = *(const float4*)(A + (size_t)(row0 + r) * GK + k0 + lq * 4);
                pb[p] = *(const float4*)(B + (size_t)(col0 + r) * GK + k0 + lq * 4);
            }
        }

        const uint32_t* Au = (const uint32_t*)(Ab + (wm * 64 + r4) * SROW + c);
        const uint32_t* Bu = (const uint32_t*)(Bb + (wn * 32 + r4) * SROW + c);

#pragma unroll
        for (int kk = 0; kk < 4; ++kk) {
            uint32_t af[4][4], bf[4][2];
            const int ko = kk * 8;
#pragma unroll
            for (int m = 0; m < 4; ++m) {
                af[m][0] = Au[(m * 16 + 0) * SROW + ko + 0];
                af[m][1] = Au[(m * 16 + 8) * SROW + ko + 0];
                af[m][2] = Au[(m * 16 + 0) * SROW + ko + 4];
                af[m][3] = Au[(m * 16 + 8) * SROW + ko + 4];
            }
#pragma unroll
            for (int n = 0; n < 4; ++n) {
                bf[n][0] = Bu[n * 8 * SROW + ko + 0];
                bf[n][1] = Bu[n * 8 * SROW + ko + 4];
            }
#pragma unroll
            for (int m = 0; m < 4; ++m)
#pragma unroll
                for (int n = 0; n < 4; ++n)
                    mma_16x8x8_tf32(acc[m][n], af[m], bf[n]);
        }

        if (i + 1 < NITER) {
            float* Aw = Asm + (buf ^ 1) * (BM * SROW);
            float* Bw = Bsm + (buf ^ 1) * (BM * SROW);
#pragma unroll
            for (int p = 0; p < 4; ++p) {
                int r = p * 32 + lrow;
                float4 va = pa[p], vb = pb[p];
                va.x = to_tf32(va.x); va.y = to_tf32(va.y);
                va.z = to_tf32(va.z); va.w = to_tf32(va.w);
                vb.x = to_tf32(vb.x); vb.y = to_tf32(vb.y);
                vb.z = to_tf32(vb.z); vb.w = to_tf32(vb.w);
                *(float4*)(Aw + r * SROW + lq * 4) = va;
                *(float4*)(Bw + r * SROW + lq * 4) = vb;
            }
            __syncthreads();
        }
    }

#pragma unroll
    for (int m = 0; m < 4; ++m) {
#pragma unroll
        for (int h = 0; h < 2; ++h) {
            const int grow = row0 + wm * 64 + m * 16 + r4 + 8 * h;
            float* crow = C + (size_t)grow * GN;
#pragma unroll
            for (int n = 0; n < 4; ++n) {
                const int gcol = col0 + wn * 32 + n * 8 + 2 * c;
                float2 o;
                o.x = acc[m][n][2 * h + 0] + __ldg(&bias[gcol + 0]);
                o.y = acc[m][n][2 * h + 1] + __ldg(&bias[gcol + 1]);
                *(float2*)(crow + gcol) = o;
            }
        }
    }
}

__global__ __launch_bounds__(256, 2) void gemm_qkv_tc(
    const float* __restrict__ x,
    const float* __restrict__ wq, const float* __restrict__ bq,
    const float* __restrict__ wk, const float* __restrict__ bk,
    const float* __restrict__ wv, const float* __restrict__ bv)
{
    const float* B; const float* bias; float* C;
    if (blockIdx.z == 0)      { B = wq; bias = bq; C = g_q; }
    else if (blockIdx.z == 1) { B = wk; bias = bk; C = g_k; }
    else                      { B = wv; bias = bv; C = g_v; }
    gemm_tc_body(x, B, bias, C);
}

__global__ __launch_bounds__(256, 2) void gemm_out_tc(
    const float* __restrict__ wo, const float* __restrict__ bo,
    float* __restrict__ out)
{
    gemm_tc_body(g_attn, wo, bo, out);
}

// ---------------------------------------------------------------------------
// Tiled windowed attention (fp32 FFMA). CTA = (64 t's, one head, one batch).
// smem: Q[64][66] | K[192][66] (reused as P[64][196]) | V[192][68] | red[64][16]
// Phase 1: S[64][192] = Qs @ Ks^T (warp grid 2Mx4N, thread 4x12)
// Phase 2: band mask + 2-pass softmax via partials
// Phase 3: out = P @ V (thread 4x4, float4 V loads), scale by 1/rowsum
// ---------------------------------------------------------------------------
__global__ __launch_bounds__(256) void attn_tile_kernel()
{
    extern __shared__ float sm[];
    float* Qs   = sm + SM_Q;
    float* Ks   = sm + SM_K;      // reused as P after softmax pass 1
    float* Vs   = sm + SM_V;
    float* red  = sm + SM_RED;    // [64][16] partials
    float* rmax = sm + SM_MAX;    // [64]
    float* rinv = sm + SM_INV;    // [64]

    const int tid = threadIdx.x;
    const int t0  = blockIdx.x * 64;
    const int nh  = blockIdx.y;
    const int h   = nh & (HH - 1);
    const int n   = nh >> 4;
    const size_t base = (size_t)n * TT * DD + (size_t)h * DHH;

    // ---- load Q (pre-scaled), K, V windows into smem ----
    for (int idx = tid; idx < 64 * 16; idx += 256) {
        int r = idx >> 4, c = (idx & 15) << 2;
        float4 v = *(const float4*)(g_q + base + (size_t)(t0 + r) * DD + c);
        float* dst = Qs + r * AQ_STRIDE + c;
        ((float2*)dst)[0] = make_float2(v.x * 0.125f, v.y * 0.125f);
        ((float2*)dst)[1] = make_float2(v.z * 0.125f, v.w * 0.125f);
    }
    for (int idx = tid; idx < 192 * 16; idx += 256) {
        int r = idx >> 4, c = (idx & 15) << 2;
        int pos = min(max(t0 - 64 + r, 0), TT - 1);
        float4 kv = *(const float4*)(g_k + base + (size_t)pos * DD + c);
        float* kd = Ks + r * AK_STRIDE + c;
        ((float2*)kd)[0] = make_float2(kv.x, kv.y);
        ((float2*)kd)[1] = make_float2(kv.z, kv.w);
        float4 vv = *(const float4*)(g_v + base + (size_t)pos * DD + c);
        *(float4*)(Vs + r * AV_STRIDE + c) = vv;    // stride 68 -> 16B aligned
    }
    __syncthreads();

    const int lane = tid & 31, wid = tid >> 5;
    const int wm = wid >> 2, wn = wid & 3;          // warps: 2(M) x 4(N)
    const int lm = lane >> 2, ln = lane & 3;        // lanes: 8(M) x 4(N)
    const int row0 = wm * 32 + lm * 4;              // 4 rows per thread
    const int colb = wn * 48 + ln * 12;             // 12 cols per thread

    // ---- phase 1: scores S = Q @ K^T ----
    float acc[4][12];
#pragma unroll
    for (int i = 0; i < 4; ++i)
#pragma unroll
        for (int j = 0; j < 12; ++j) acc[i][j] = 0.f;

    const float* Qp = Qs + row0 * AQ_STRIDE;
    const float* Kp = Ks + colb * AK_STRIDE;
    for (int k2 = 0; k2 < 32; ++k2) {
        float2 a[4], b[12];
#pragma unroll
        for (int i = 0; i < 4; ++i)
            a[i] = *(const float2*)(Qp + i * AQ_STRIDE + 2 * k2);
#pragma unroll
        for (int j = 0; j < 12; ++j)
            b[j] = *(const float2*)(Kp + j * AK_STRIDE + 2 * k2);
#pragma unroll
        for (int i = 0; i < 4; ++i)
#pragma unroll
            for (int j = 0; j < 12; ++j)
                acc[i][j] += a[i].x * b[j].x + a[i].y * b[j].y;
    }

    // ---- phase 2: band mask + softmax (2-pass, cross-warp via partials) ----
    const int lob = 64 - t0;           // global pos >= 0
    const int hib = 1087 - t0;         // global pos < TT
#pragma unroll
    for (int i = 0; i < 4; ++i) {
        int row = row0 + i;
        int lo = max(row, lob), hi = min(row + 128, hib);
        float m = -1e30f;
#pragma unroll
        for (int j = 0; j < 12; ++j) {
            int c = colb + j;
            if (c < lo || c > hi) acc[i][j] = -1e30f;
            m = fmaxf(m, acc[i][j]);
        }
        red[row * 16 + wn * 4 + ln] = m;
    }
    __syncthreads();
    if (tid < 64) {
        float m = red[tid * 16];
#pragma unroll
        for (int p = 1; p < 16; ++p) m = fmaxf(m, red[tid * 16 + p]);
        rmax[tid] = m;
    }
    __syncthreads();

    float* Ps = Ks;   // K no longer needed
#pragma unroll
    for (int i = 0; i < 4; ++i) {
        int row = row0 + i;
        float m = rmax[row];
        float s = 0.f;
        float* pd = Ps + row * AP_STRIDE + colb;
#pragma unroll
        for (int j = 0; j < 12; ++j) {
            float e = __expf(acc[i][j] - m);   // masked -> exp(-huge)=0
            s += e;
            pd[j] = e;
        }
        red[row * 16 + wn * 4 + ln] = s;
    }
    __syncthreads();
    if (tid < 64) {
        float s = 0.f;
#pragma unroll
        for (int p = 0; p < 16; ++p) s += red[tid * 16 + p];
        rinv[tid] = 1.0f / s;
    }
    __syncthreads();

    // ---- phase 3: out = P @ V ----
    const int d0 = wn * 16 + ln * 4;   // 4 dh cols per thread
    float pv[4][4];
#pragma unroll
    for (int i = 0; i < 4; ++i)
#pragma unroll
        for (int j = 0; j < 4; ++j) pv[i][j] = 0.f;

    const float* Pp = Ps + row0 * AP_STRIDE;
    for (int k2 = 0; k2 < 96; ++k2) {
        float2 a[4];
#pragma unroll
        for (int i = 0; i < 4; ++i)
            a[i] = *(const float2*)(Pp + i * AP_STRIDE + 2 * k2);
        float4 b0 = *(const float4*)(Vs + (2 * k2 + 0) * AV_STRIDE + d0);
        float4 b1 = *(const float4*)(Vs + (2 * k2 + 1) * AV_STRIDE + d0);
#pragma unroll
        for (int i = 0; i < 4; ++i) {
            pv[i][0] += a[i].x * b0.x + a[i].y * b1.x;
            pv[i][1] += a[i].x * b0.y + a[i].y * b1.y;
            pv[i][2] += a[i].x * b0.z + a[i].y * b1.z;
            pv[i][3] += a[i].x * b0.w + a[i].y * b1.w;
        }
    }

#pragma unroll
    for (int i = 0; i < 4; ++i) {
        int row = row0 + i;
        float inv = rinv[row];
        float4 o = make_float4(pv[i][0] * inv, pv[i][1] * inv,
                               pv[i][2] * inv, pv[i][3] * inv);
        *(float4*)(g_attn + base + (size_t)(t0 + row) * DD + d0) = o;
    }
}

// ---------------- launch ----------------
extern "C" void kernel_launch(void* const* d_in, const int* in_sizes, int n_in,
                              void* d_out, int out_size)
{
    const float* x  = (const float*)d_in[0];
    const float* wq = (const float*)d_in[1];
    const float* bq = (const float*)d_in[2];
    const float* wk = (const float*)d_in[3];
    const float* bk = (const float*)d_in[4];
    const float* wv = (const float*)d_in[5];
    const float* bv = (const float*)d_in[6];
    const float* wo = (const float*)d_in[7];
    const float* bo = (const float*)d_in[8];

    cudaFuncSetAttribute(gemm_qkv_tc,
                         cudaFuncAttributeMaxDynamicSharedMemorySize, SMEM_BYTES);
    cudaFuncSetAttribute(gemm_out_tc,
                         cudaFuncAttributeMaxDynamicSharedMemorySize, SMEM_BYTES);
    cudaFuncSetAttribute(attn_tile_kernel,
                         cudaFuncAttributeMaxDynamicSharedMemorySize, ATT_SMEM_BYTES);

    dim3 gq(GN / BN, GM / BM, 3);
    gemm_qkv_tc<<<gq, 256, SMEM_BYTES>>>(x, wq, bq, wk, bk, wv, bv);

    attn_tile_kernel<<<dim3(TT / 64, NB * HH), 256, ATT_SMEM_BYTES>>>();

    dim3 go(GN / BN, GM / BM);
    gemm_out_tc<<<go, 256, SMEM_BYTES>>>(wo, bo, (float*)d_out);
}